// round 8
// baseline (speedup 1.0000x reference)
#include <cuda_runtime.h>

#define Bp 400
#define Np 8000
#define Dp 100
#define SCALERp 4

#define TILE 8                 // rows per register tile
#define WARPS 4
#define THREADS 128
#define TILES_PER_WARP 50      // 400 rows per warp; 48 pipelined + 2 epilogue
#define ROWS_PER_BLOCK (WARPS * TILE * TILES_PER_WARP)   // 1600
#define BLOCKS_PER_B (Np / ROWS_PER_BLOCK)               // 5
#define TOTAL_BLOCKS (Bp * BLOCKS_PER_B)                 // 2000
#define RSTRIDE 27             // gcd(27,32)=1 -> conflict-free transpose

// Deterministic per-(b,chunk) pooled partials: [B][BLOCKS_PER_B][D]
__device__ float g_partial[Bp * BLOCKS_PER_B * Dp];
__device__ int   g_cnt = 0;    // last-block election; self-resetting each launch

__device__ __forceinline__ float tanh_approx(float x) {
    float y;
    asm("tanh.approx.f32 %0, %1;" : "=f"(y) : "f"(x));
    return y;
}

__device__ __forceinline__ void load_tile(float4 (&v)[TILE],
                                          const float4* __restrict__ base4,
                                          int lane)
{
    if (lane < 25) {
        #pragma unroll
        for (int r = 0; r < TILE; r++) v[r] = base4[r * 25 + lane];
    }
}

__device__ __forceinline__ void compute_tile(const float4 (&v)[TILE],
                                             int n0, long long rowbase,
                                             int lane, bool redlane, int col,
                                             const float4 dw4, const float4 w14,
                                             float* __restrict__ buf,
                                             float4& acc,
                                             float* __restrict__ alpha_out,
                                             float* __restrict__ beta_out)
{
    // Partial dots straight into the stride-27 transpose buffer
    if (lane < 25) {
        #pragma unroll
        for (int r = 0; r < TILE; r++) {
            const float4 q = v[r];
            buf[lane * RSTRIDE + r] =
                q.x * dw4.x + q.y * dw4.y + q.z * dw4.z + q.w * dw4.w;
            buf[lane * RSTRIDE + TILE + r] =
                q.x * w14.x + q.y * w14.y + q.z * w14.z + q.w * w14.w;
        }
    }
    __syncwarp();

    // Merged reduce: lanes 0-7 sum pa(row=lane), lanes 16-23 sum pb
    float sum = 0.f;
    if (redlane) {
        #pragma unroll
        for (int l = 0; l < 25; l++) sum += buf[l * RSTRIDE + col];
    }
    const float a = tanh_approx(sum);   // valid in lanes 0..7
    if (lane < 8)
        alpha_out[rowbase + n0 + lane] = a;
    else if (redlane)
        beta_out[rowbase + n0 + (lane - 16)] = sum;

    // Pooled accumulation from registers
    #pragma unroll
    for (int r = 0; r < TILE; r++) {
        const float ar = __shfl_sync(0xffffffffu, a, r);
        const float4 q = v[r];
        acc.x += ar * q.x;
        acc.y += ar * q.y;
        acc.z += ar * q.z;
        acc.w += ar * q.w;
    }
    __syncwarp();   // protect buf before the next tile overwrites it
}

__global__ __launch_bounds__(THREADS)
void fused_pass_kernel(const float* __restrict__ x,
                       const float* __restrict__ x_scaler,
                       const float* __restrict__ dim_weight,
                       const float* __restrict__ w,
                       float* __restrict__ out_small,
                       float* __restrict__ alpha_out,
                       float* __restrict__ beta_out)
{
    const int b    = blockIdx.x / BLOCKS_PER_B;
    const int c    = blockIdx.x % BLOCKS_PER_B;
    const int warp = threadIdx.x >> 5;
    const int lane = threadIdx.x & 31;

    __shared__ float s_red[WARPS][25 * RSTRIDE];  // 10.8 KB: pa|pb transpose
    __shared__ float s_acc[WARPS][Dp];            //  1.6 KB
    __shared__ bool  s_last;

    // Lane l (<25) owns dims [4l, 4l+4)
    float4 dw4 = make_float4(0.f, 0.f, 0.f, 0.f);
    float4 w14 = make_float4(0.f, 0.f, 0.f, 0.f);
    if (lane < 25) {
        dw4 = *reinterpret_cast<const float4*>(dim_weight + 4 * lane);
        w14.x = w[(4 * lane + 0) * 2 + 1];
        w14.y = w[(4 * lane + 1) * 2 + 1];
        w14.z = w[(4 * lane + 2) * 2 + 1];
        w14.w = w[(4 * lane + 3) * 2 + 1];
    }

    float4 acc = make_float4(0.f, 0.f, 0.f, 0.f);
    float* buf = s_red[warp];
    const long long rowbase = (long long)b * Np;

    const bool redlane = (lane < 8) | ((lane >= 16) & (lane < 24));
    const int  col     = (lane & 7) + ((lane >= 16) ? 8 : 0);

    // Tile t covers rows n0(t) = c*ROWS_PER_BLOCK + (t*WARPS + warp)*TILE
    const int  nbase = c * ROWS_PER_BLOCK + warp * TILE;
    #define N0(t)   (nbase + (t) * (WARPS * TILE))
    #define BASE4(t) (reinterpret_cast<const float4*>(x + (rowbase + N0(t)) * Dp))

    float4 v0[TILE], v1[TILE], v2[TILE];

    // Prologue: tiles 0 and 1 in flight
    load_tile(v0, BASE4(0), lane);
    load_tile(v1, BASE4(1), lane);

    // Main loop: depth-3 rotation, unrolled by 3.
    // Step i: prefetch tile i+2 (into the buffer freed at step i-1), compute tile i.
    // Max prefetch index = 49 -> no bounds checks needed.
    for (int t = 0; t < TILES_PER_WARP - 2; t += 3) {
        load_tile(v2, BASE4(t + 2), lane);
        compute_tile(v0, N0(t),     rowbase, lane, redlane, col, dw4, w14, buf, acc, alpha_out, beta_out);
        load_tile(v0, BASE4(t + 3), lane);
        compute_tile(v1, N0(t + 1), rowbase, lane, redlane, col, dw4, w14, buf, acc, alpha_out, beta_out);
        load_tile(v1, BASE4(t + 4), lane);
        compute_tile(v2, N0(t + 2), rowbase, lane, redlane, col, dw4, w14, buf, acc, alpha_out, beta_out);
    }
    // Epilogue: tiles 48, 49 (already loaded in the last macro-iteration)
    compute_tile(v0, N0(TILES_PER_WARP - 2), rowbase, lane, redlane, col, dw4, w14, buf, acc, alpha_out, beta_out);
    compute_tile(v1, N0(TILES_PER_WARP - 1), rowbase, lane, redlane, col, dw4, w14, buf, acc, alpha_out, beta_out);

    // ---- Block-reduce the 4 warp accumulators (deterministic)
    if (lane < 25) {
        s_acc[warp][lane * 4 + 0] = acc.x;
        s_acc[warp][lane * 4 + 1] = acc.y;
        s_acc[warp][lane * 4 + 2] = acc.z;
        s_acc[warp][lane * 4 + 3] = acc.w;
    }
    __syncthreads();
    for (int d = threadIdx.x; d < Dp; d += THREADS) {
        float sum = 0.f;
        #pragma unroll
        for (int wp = 0; wp < WARPS; wp++) sum += s_acc[wp][d];
        g_partial[((long long)b * BLOCKS_PER_B + c) * Dp + d] = sum;
    }

    // ---- Last-arriving block performs the final [B,2] head (deterministic)
    __threadfence();
    if (threadIdx.x == 0) {
        int old = atomicAdd(&g_cnt, 1);
        s_last = (old == TOTAL_BLOCKS - 1);
    }
    __syncthreads();
    if (!s_last) return;
    if (threadIdx.x == 0) g_cnt = 0;      // reset for next graph replay

    for (int b2 = warp; b2 < Bp; b2 += WARPS) {
        float4 f4 = make_float4(0.f, 0.f, 0.f, 0.f);
        if (lane < 25) {
            #pragma unroll
            for (int cc = 0; cc < BLOCKS_PER_B; cc++) {
                const float4 g = *reinterpret_cast<const float4*>(
                    g_partial + ((long long)b2 * BLOCKS_PER_B + cc) * Dp + 4 * lane);
                f4.x += g.x; f4.y += g.y; f4.z += g.z; f4.w += g.w;
            }
        }
        float p0 = 0.f, p1 = 0.f;
        if (lane < 25) {
            p0 = f4.x * w[(4*lane+0)*2+0] + f4.y * w[(4*lane+1)*2+0]
               + f4.z * w[(4*lane+2)*2+0] + f4.w * w[(4*lane+3)*2+0];
            p1 = f4.x * w[(4*lane+0)*2+1] + f4.y * w[(4*lane+1)*2+1]
               + f4.z * w[(4*lane+2)*2+1] + f4.w * w[(4*lane+3)*2+1];
        }
        #pragma unroll
        for (int off = 16; off; off >>= 1) {
            p0 += __shfl_xor_sync(0xffffffffu, p0, off);
            p1 += __shfl_xor_sync(0xffffffffu, p1, off);
        }
        if (lane == 0) {
            #pragma unroll
            for (int s = 0; s < SCALERp; s++) {
                const float xs = x_scaler[b2 * SCALERp + s];
                p0 += xs * w[(Dp + s) * 2 + 0];
                p1 += xs * w[(Dp + s) * 2 + 1];
            }
            out_small[b2 * 2 + 0] = p0;
            out_small[b2 * 2 + 1] = p1;
        }
    }
}

extern "C" void kernel_launch(void* const* d_in, const int* in_sizes, int n_in,
                              void* d_out, int out_size)
{
    // metadata order == setup_inputs order: x, x_scaler, dim_weight, w
    const float* x          = (const float*)d_in[0];
    const float* x_scaler   = (const float*)d_in[1];
    const float* dim_weight = (const float*)d_in[2];
    const float* w          = (const float*)d_in[3];

    // Output flattening in reference-return order: out [B,2], alpha [B,1,N], beta [B,N]
    float* out_base  = (float*)d_out;
    float* out_small = out_base;                       // 800 floats
    float* alpha     = out_base + Bp * 2;              // 3,200,000 floats
    float* beta      = alpha + (long long)Bp * Np;     // 3,200,000 floats

    fused_pass_kernel<<<TOTAL_BLOCKS, THREADS>>>(
        x, x_scaler, dim_weight, w, out_small, alpha, beta);
}